// round 5
// baseline (speedup 1.0000x reference)
#include <cuda_runtime.h>
#include <cstdint>
#include <cstddef>

// Problem constants
#define Bsz 16
#define Ssz 512
#define Nent 64
#define Hdim 768
#define HH 384          // H/2
#define ET 9
#define RT 10
#define NPAIR 2016      // 64*63/2
#define MS (Bsz*Ssz)    // 8192
#define ME (Bsz*Nent)   // 1024
#define PAIRN (2*Hdim)  // 1536

// Scratch (static device arrays — allocation-free rule)
__device__ float g_hidden[(size_t)MS * HH];            // relu(seq@W1e+b1e)
__device__ float g_pK[2][(size_t)ME * PAIRN];          // split-K partials
__device__ float g_pAT[(size_t)Bsz * Hdim * Nent];     // pA transposed [b][k][n]
__device__ float g_pBT[(size_t)Bsz * Hdim * Nent];     // pB transposed [b][k][n]
__device__ int   g_pairs[NPAIR * 2];

// ===========================================================================
// Packed fp32x2 + cp.async helpers (base-ISA PTX, compiles for compute_103)
// ===========================================================================
__device__ __forceinline__ void ffma2(unsigned long long& d,
                                      unsigned long long a,
                                      unsigned long long b) {
    asm("fma.rn.f32x2 %0, %1, %2, %0;" : "+l"(d) : "l"(a), "l"(b));
}
__device__ __forceinline__ unsigned long long dup2(float x) {
    unsigned long long r; unsigned u = __float_as_uint(x);
    asm("mov.b64 %0, {%1, %1};" : "=l"(r) : "r"(u));
    return r;
}
__device__ __forceinline__ float2 unpack2(unsigned long long v) {
    unsigned lo, hi;
    asm("mov.b64 {%0, %1}, %2;" : "=r"(lo), "=r"(hi) : "l"(v));
    return make_float2(__uint_as_float(lo), __uint_as_float(hi));
}
__device__ __forceinline__ uint32_t smem_u32(const void* p) {
    uint32_t a;
    asm("{ .reg .u64 t; cvta.to.shared.u64 t, %1; cvt.u32.u64 %0, t; }"
        : "=r"(a) : "l"(p));
    return a;
}
__device__ __forceinline__ void cp_async16(uint32_t saddr, const void* gaddr) {
    asm volatile("cp.async.cg.shared.global [%0], [%1], 16;"
                 :: "r"(saddr), "l"(gaddr) : "memory");
}
#define CP_COMMIT() asm volatile("cp.async.commit_group;" ::: "memory")
#define CP_WAIT0()  asm volatile("cp.async.wait_group 0;" ::: "memory")

// ===========================================================================
// FFMA2 SGEMM: C = op(A[M,K] @ B[K,N] + bias), row-major fp32.
// CTA tile 64x64, BK=32, 128 threads, microtile 4 rows x 8 cols.
// Accumulators are col-pairs (b64); B pairs load packed from smem (no movs),
// A scalars get 4 dup-movs per k. A is LDG->STS transposed+swizzled;
// B streams via cp.async. gridDim=(N/64, M/64, SPLITZ); z splits K and
// writes its own C plane at C + z*zCoff.
// B operand concat support: column tile bn >= ncat reads B2 at (bn - ncat).
// ===========================================================================
#define GTM 64
#define GTN 64
#define GTK 32
#define ASTRIDE 68                     // words per k-row of A smem
#define ASTAGE (GTK*ASTRIDE)           // 2176 floats
#define BSTAGE (GTK*GTN)               // 2048 floats
#define GEMM_SMEM ((2*ASTAGE + 2*BSTAGE) * 4)   // 33792 bytes

template<bool RELU, bool HASBIAS>
__global__ __launch_bounds__(128, 4) void gemm_f2(
    const float* __restrict__ A, int lda,
    const float* __restrict__ B, const float* __restrict__ B2,
    int ncat, int ldb,
    const float* __restrict__ bias,
    float* __restrict__ C, int ldc,
    int Kper, size_t zCoff)
{
    extern __shared__ float sm[];
    float* smA = sm;                   // 2 stages x ASTAGE
    float* smB = sm + 2 * ASTAGE;      // 2 stages x BSTAGE

    const int tid = threadIdx.x;
    const int row0 = (tid >> 3) * 4;   // 0..60
    const int col0 = (tid & 7) * 8;    // 0..56

    const int bm = blockIdx.y * GTM;
    int bn = blockIdx.x * GTN;
    const int z = blockIdx.z;

    const float* Bsel = B;
    if (bn >= ncat) { Bsel = B2; bn -= ncat; }

    const float* Ab = A + (size_t)z * Kper + (size_t)bm * lda;
    const float* Bb = Bsel + (size_t)z * Kper * ldb + bn;
    float* Cb = C + (size_t)z * zCoff;
    const int colg0 = blockIdx.x * GTN;   // output column base (pre-concat-adjust)

    unsigned long long acc[4][4];      // [row][col-pair]
#pragma unroll
    for (int r = 0; r < 4; r++)
#pragma unroll
        for (int c = 0; c < 4; c++) acc[r][c] = 0ull;

    const int CH = Kper / GTK;
    float4 ra[4];

    // A: 64x32 tile = 512 float4; idx=q*128+tid -> m=idx>>3, kq=(idx&7)*4
#define LDG_A(k0) do { \
    _Pragma("unroll") \
    for (int q = 0; q < 4; q++) { \
        int idx = q * 128 + tid; \
        int m = idx >> 3, kq = (idx & 7) << 2; \
        ra[q] = *(const float4*)(Ab + (size_t)m * lda + (k0) + kq); \
    } \
} while (0)
    // STS transposed + swizzle: addr(k,m) = k*68 + (m ^ (k & 28))
#define STS_A(dst) do { \
    _Pragma("unroll") \
    for (int q = 0; q < 4; q++) { \
        int idx = q * 128 + tid; \
        int m = idx >> 3, kq = (idx & 7) << 2; \
        int ms = m ^ kq; \
        (dst)[(kq + 0) * ASTRIDE + ms] = ra[q].x; \
        (dst)[(kq + 1) * ASTRIDE + ms] = ra[q].y; \
        (dst)[(kq + 2) * ASTRIDE + ms] = ra[q].z; \
        (dst)[(kq + 3) * ASTRIDE + ms] = ra[q].w; \
    } \
} while (0)
    // B: 32x64 tile = 512 float4; idx=q*128+tid -> k=idx>>4, c4=(idx&15)*4
#define CPA_B(k0, stB) do { \
    uint32_t sb = smem_u32(smB + (stB) * BSTAGE) + (uint32_t)tid * 16u; \
    _Pragma("unroll") \
    for (int q = 0; q < 4; q++) { \
        int idx = q * 128 + tid; \
        int k = idx >> 4, c4 = (idx & 15) << 2; \
        cp_async16(sb + q * 2048u, Bb + (size_t)((k0) + k) * ldb + c4); \
    } \
    CP_COMMIT(); \
} while (0)

    // ---- prologue ----
    CPA_B(0, 0);
    LDG_A(0);
    STS_A(smA);
    CP_WAIT0();
    __syncthreads();

    for (int c = 0; c < CH; c++) {
        const int st = c & 1;
        const int nx = st ^ 1;
        if (c + 1 < CH) {
            CPA_B((c + 1) * GTK, nx);
            LDG_A((c + 1) * GTK);
        }

        const float* Asm = smA + st * ASTAGE;
        const float* Bsm = smB + st * BSTAGE;
#pragma unroll
        for (int k = 0; k < GTK; k++) {
            const int sw = k & 28;
            float4 a = *(const float4*)&Asm[k * ASTRIDE + (row0 ^ sw)];
            ulonglong2 b0 = *(const ulonglong2*)&Bsm[k * GTN + col0];
            ulonglong2 b1 = *(const ulonglong2*)&Bsm[k * GTN + col0 + 4];
            unsigned long long ad[4] = {dup2(a.x), dup2(a.y), dup2(a.z), dup2(a.w)};
            unsigned long long bp[4] = {b0.x, b0.y, b1.x, b1.y};
#pragma unroll
            for (int r = 0; r < 4; r++)
#pragma unroll
                for (int cc = 0; cc < 4; cc++)
                    ffma2(acc[r][cc], ad[r], bp[cc]);
        }

        if (c + 1 < CH) STS_A(smA + nx * ASTAGE);
        CP_WAIT0();
        __syncthreads();
    }

    // ---- epilogue ----
    const int colg = colg0 + col0;
    float bb[8] = {0, 0, 0, 0, 0, 0, 0, 0};
    if (HASBIAS) {
        float4 t0 = *(const float4*)(bias + colg);
        float4 t1 = *(const float4*)(bias + colg + 4);
        bb[0] = t0.x; bb[1] = t0.y; bb[2] = t0.z; bb[3] = t0.w;
        bb[4] = t1.x; bb[5] = t1.y; bb[6] = t1.z; bb[7] = t1.w;
    }
#pragma unroll
    for (int r = 0; r < 4; r++) {
        float o[8];
#pragma unroll
        for (int cc = 0; cc < 4; cc++) {
            float2 v = unpack2(acc[r][cc]);
            o[cc * 2]     = v.x + bb[cc * 2];
            o[cc * 2 + 1] = v.y + bb[cc * 2 + 1];
        }
        if (RELU) {
#pragma unroll
            for (int q = 0; q < 8; q++) o[q] = fmaxf(o[q], 0.f);
        }
        float* Crow = Cb + (size_t)(bm + row0 + r) * ldc + colg;
        *(float4*)Crow = make_float4(o[0], o[1], o[2], o[3]);
        *(float4*)(Crow + 4) = make_float4(o[4], o[5], o[6], o[7]);
    }
#undef LDG_A
#undef STS_A
#undef CPA_B
}

// ===========================================================================
// Prep: pair index table
// ===========================================================================
__global__ void prep_pairs_kernel()
{
    int p = blockIdx.x * blockDim.x + threadIdx.x;
    if (p >= NPAIR) return;
    int rem = p, i = 0;
    while (rem >= (Nent - 1) - i) { rem -= (Nent - 1) - i; i++; }
    g_pairs[p * 2]     = i;
    g_pairs[p * 2 + 1] = i + 1 + rem;
}

// ===========================================================================
// Combine split-K + bias + transpose:
//  in:  pK[0]+pK[1] at [e=(b,n)][k'] (k'<768 -> pA + b1r, else pB)
//  out: pAT[b][k][n], pBT[b][k][n]
// ===========================================================================
__global__ __launch_bounds__(256) void combine_transpose_kernel(
    const float* __restrict__ b1r)
{
    __shared__ float t[32][33];
    const int kb = blockIdx.x * 32;        // k' base 0..1535
    const int eb = blockIdx.y * 32;        // entity-row base 0..1023
    const int tx = threadIdx.x & 31;
    const int ty = threadIdx.x >> 5;       // 0..7

#pragma unroll
    for (int s = 0; s < 4; s++) {
        int e = eb + ty + s * 8;
        size_t off = (size_t)e * PAIRN + kb + tx;
        t[ty + s * 8][tx] = g_pK[0][off] + g_pK[1][off];
    }
    __syncthreads();

    const int b = eb >> 6;
    const int n0 = eb & 63;
#pragma unroll
    for (int s = 0; s < 4; s++) {
        int kk = kb + ty + s * 8;
        float v = t[tx][ty + s * 8];
        if (kk < Hdim) {
            v += b1r[kk];
            g_pAT[((size_t)b * Hdim + kk) * Nent + n0 + tx] = v;
        } else {
            g_pBT[((size_t)b * Hdim + (kk - Hdim)) * Nent + n0 + tx] = v;
        }
    }
}

// ===========================================================================
// entity_logits = hidden[8192,384] @ W2e[384,9] + b2e. Warp per row.
// ===========================================================================
__global__ __launch_bounds__(256) void entity_logits_kernel(
    const float* __restrict__ hidden, const float* __restrict__ W2e,
    const float* __restrict__ b2e, float* __restrict__ out)
{
    __shared__ float W2s[HH * ET];
    const int tid = threadIdx.x;
    for (int i = tid; i < HH * ET; i += 256) W2s[i] = W2e[i];
    __syncthreads();

    const int warp = tid >> 5, lane = tid & 31;
    const int row = blockIdx.x * 8 + warp;
    const float* hrow = hidden + (size_t)row * HH;

    float acc[ET];
#pragma unroll
    for (int c = 0; c < ET; c++) acc[c] = 0.f;

#pragma unroll
    for (int kk = 0; kk < HH / 32; kk++) {
        int k = kk * 32 + lane;
        float h = hrow[k];
        const float* w = &W2s[k * ET];
#pragma unroll
        for (int c = 0; c < ET; c++) acc[c] += h * w[c];
    }
#pragma unroll
    for (int c = 0; c < ET; c++)
#pragma unroll
        for (int off = 16; off > 0; off >>= 1)
            acc[c] += __shfl_down_sync(0xffffffffu, acc[c], off);

    if (lane == 0) {
        float* o = out + (size_t)row * ET;
#pragma unroll
        for (int c = 0; c < ET; c++) o[c] = acc[c] + b2e[c];
    }
}

// ===========================================================================
// Span mean pooling, fixed 16-iteration predicated loop.
// ===========================================================================
__global__ __launch_bounds__(192) void span_pool_kernel(
    const float4* __restrict__ seq4, const int* __restrict__ spans,
    float4* __restrict__ er4)
{
    const int bn = blockIdx.x;
    const int b = bn >> 6;
    const int s0 = spans[bn * 2];
    const int s1 = spans[bn * 2 + 1];
    int cnt = s1 - s0; if (cnt < 1) cnt = 1;
    const float inv = 1.f / (float)cnt;
    const float4* base = seq4 + (size_t)b * Ssz * (Hdim / 4) + threadIdx.x;

    float4 acc = make_float4(0.f, 0.f, 0.f, 0.f);
#pragma unroll
    for (int q = 0; q < 16; q++) {
        int s = s0 + q;
        float4 v = base[(size_t)s * (Hdim / 4)];
        if (s < s1) { acc.x += v.x; acc.y += v.y; acc.z += v.z; acc.w += v.w; }
    }
    acc.x *= inv; acc.y *= inv; acc.z *= inv; acc.w *= inv;
    er4[(size_t)bn * (Hdim / 4) + threadIdx.x] = acc;
}

// ===========================================================================
// relation_logits: thread per pair, W2 broadcast from smem, FFMA2 accs.
// h(k) = relu(pAT[b][k][i] + pBT[b][k][j]);  logits = h @ W2r + b2r
// ===========================================================================
__global__ __launch_bounds__(256) void relation_kernel(
    const float* __restrict__ W2r, const float* __restrict__ b2r,
    float* __restrict__ out)
{
    __shared__ __align__(16) float Wp[Hdim * 12];      // [k][12] padded
    const int tid = threadIdx.x;
    for (int idx = tid; idx < Hdim * 12; idx += 256) {
        int k = idx / 12, c = idx % 12;
        Wp[idx] = (c < RT) ? W2r[k * RT + c] : 0.f;
    }
    __syncthreads();

    const int b = blockIdx.y;
    const int p = blockIdx.x * 256 + tid;
    const bool act = (p < NPAIR);
    int i = 0, j = 0;
    if (act) { i = g_pairs[p * 2]; j = g_pairs[p * 2 + 1]; }

    const float* At = g_pAT + (size_t)b * Hdim * Nent;
    const float* Bt = g_pBT + (size_t)b * Hdim * Nent;

    unsigned long long acc[6];
#pragma unroll
    for (int c = 0; c < 6; c++) acc[c] = 0ull;

#pragma unroll 4
    for (int k = 0; k < Hdim; k++) {
        float h = fmaxf(At[(size_t)k * Nent + i] + Bt[(size_t)k * Nent + j], 0.f);
        unsigned long long hd = dup2(h);
        const ulonglong2* w = (const ulonglong2*)&Wp[k * 12];
        ulonglong2 w0 = w[0], w1 = w[1], w2 = w[2];
        ffma2(acc[0], hd, w0.x); ffma2(acc[1], hd, w0.y);
        ffma2(acc[2], hd, w1.x); ffma2(acc[3], hd, w1.y);
        ffma2(acc[4], hd, w2.x); ffma2(acc[5], hd, w2.y);
    }

    if (act) {
        float o[12];
#pragma unroll
        for (int c = 0; c < 6; c++) {
            float2 v = unpack2(acc[c]);
            o[c * 2] = v.x; o[c * 2 + 1] = v.y;
        }
        float* dst = out + (size_t)(b * NPAIR + p) * RT;
#pragma unroll
        for (int c = 0; c < RT; c++) dst[c] = o[c] + b2r[c];
    }
}

// ===========================================================================
extern "C" void kernel_launch(void* const* d_in, const int* in_sizes, int n_in,
                              void* d_out, int out_size)
{
    const float* seq   = (const float*)d_in[0];
    const int*   spans = (const int*)d_in[2];
    const float* W1e   = (const float*)d_in[3];
    const float* b1e   = (const float*)d_in[4];
    const float* W2e   = (const float*)d_in[5];
    const float* b2e   = (const float*)d_in[6];
    const float* W1r   = (const float*)d_in[7];
    const float* b1r   = (const float*)d_in[8];
    const float* W2r   = (const float*)d_in[9];
    const float* b2r   = (const float*)d_in[10];

    float* out = (float*)d_out;
    float* EL = out;                                   // [16,512,9]
    float* ER = out + (size_t)MS * ET;                 // [16,64,768]
    float* RL = ER + (size_t)ME * Hdim;                // [16,2016,10]

    void *p_hidden, *p_pK;
    cudaGetSymbolAddress(&p_hidden, g_hidden);
    cudaGetSymbolAddress(&p_pK, g_pK);
    float* hidden = (float*)p_hidden;

    cudaFuncSetAttribute(gemm_f2<true, true>,
                         cudaFuncAttributeMaxDynamicSharedMemorySize, GEMM_SMEM);
    cudaFuncSetAttribute(gemm_f2<false, false>,
                         cudaFuncAttributeMaxDynamicSharedMemorySize, GEMM_SMEM);

    // Prep
    prep_pairs_kernel<<<(NPAIR + 255) / 256, 256>>>();

    // entity_repr (output + input of pair GEMM)
    span_pool_kernel<<<Bsz * Nent, 192>>>((const float4*)seq, spans, (float4*)ER);

    // hidden = relu(seq @ W1e + b1e)   [8192,384]   768 CTAs
    gemm_f2<true, true><<<dim3(HH / GTN, MS / GTM, 1), 128, GEMM_SMEM>>>(
        seq, Hdim, W1e, nullptr, 1 << 30, HH, b1e, hidden, HH, Hdim, 0);

    // entity_logits = hidden @ W2e + b2e
    entity_logits_kernel<<<MS / 8, 256>>>(hidden, W2e, b2e, EL);

    // pK[z] = ER @ [W1r_top | W1r_bot](z-slice)   split-K=2, 768 CTAs
    gemm_f2<false, false><<<dim3(PAIRN / GTN, ME / GTM, 2), 128, GEMM_SMEM>>>(
        ER, Hdim, W1r, W1r + (size_t)Hdim * Hdim, Hdim, Hdim, nullptr,
        (float*)p_pK, PAIRN, Hdim / 2, (size_t)ME * PAIRN);

    // pAT/pBT = transpose(pK[0] + pK[1] + [b1r | 0])
    combine_transpose_kernel<<<dim3(PAIRN / 32, ME / 32), 256>>>(b1r);

    // relation_logits
    relation_kernel<<<dim3((NPAIR + 255) / 256, Bsz), 256>>>(W2r, b2r, RL);
}

// round 6
// speedup vs baseline: 1.2871x; 1.2871x over previous
#include <cuda_runtime.h>
#include <cstdint>
#include <cstddef>

// Problem constants
#define Bsz 16
#define Ssz 512
#define Nent 64
#define Hdim 768
#define HH 384          // H/2
#define ET 9
#define RT 10
#define NPAIR 2016      // 64*63/2
#define MS (Bsz*Ssz)    // 8192
#define ME (Bsz*Nent)   // 1024
#define PAIRN (2*Hdim)  // 1536

// Scratch (static device arrays — allocation-free rule)
__device__ float g_hidden[(size_t)MS * HH];            // relu(seq@W1e+b1e)
__device__ float g_pK[2][(size_t)ME * PAIRN];          // split-K partials
__device__ float g_pAT[(size_t)Bsz * Hdim * Nent];     // pA transposed [b][k][n]
__device__ float g_pBT[(size_t)Bsz * Hdim * Nent];     // pB transposed [b][k][n]
__device__ int   g_pairs[NPAIR * 2];

// ===========================================================================
// Helpers (base-ISA PTX only — compiles through compute_103 virtual arch)
// ===========================================================================
__device__ __forceinline__ uint32_t smem_u32(const void* p) {
    uint32_t a;
    asm("{ .reg .u64 t; cvta.to.shared.u64 t, %1; cvt.u32.u64 %0, t; }"
        : "=r"(a) : "l"(p));
    return a;
}
__device__ __forceinline__ void cp_async16(uint32_t saddr, const void* gaddr) {
    asm volatile("cp.async.cg.shared.global [%0], [%1], 16;"
                 :: "r"(saddr), "l"(gaddr) : "memory");
}
#define CP_COMMIT() asm volatile("cp.async.commit_group;" ::: "memory")
#define CP_WAIT(n)  asm volatile("cp.async.wait_group %0;" :: "n"(n) : "memory")

__device__ __forceinline__ uint32_t tf32u(float x) {
    uint32_t o;
    asm("cvt.rna.tf32.f32 %0, %1;" : "=r"(o) : "f"(x));
    return o;
}
// D += A(tf32) @ B(tf32), m16n8k8, fp32 accumulate — tensor pipe (HMMA)
__device__ __forceinline__ void mma_tf32(float4& d, const uint32_t* a,
                                         uint32_t b0, uint32_t b1) {
    asm volatile(
        "mma.sync.aligned.m16n8k8.row.col.f32.tf32.tf32.f32 "
        "{%0,%1,%2,%3}, {%4,%5,%6,%7}, {%8,%9}, {%0,%1,%2,%3};"
        : "+f"(d.x), "+f"(d.y), "+f"(d.z), "+f"(d.w)
        : "r"(a[0]), "r"(a[1]), "r"(a[2]), "r"(a[3]), "r"(b0), "r"(b1));
}

// fp32x2 helpers (relation kernel)
__device__ __forceinline__ void ffma2(unsigned long long& d,
                                      unsigned long long a,
                                      unsigned long long b) {
    asm("fma.rn.f32x2 %0, %1, %2, %0;" : "+l"(d) : "l"(a), "l"(b));
}
__device__ __forceinline__ unsigned long long dup2(float x) {
    unsigned long long r; unsigned u = __float_as_uint(x);
    asm("mov.b64 %0, {%1, %1};" : "=l"(r) : "r"(u));
    return r;
}
__device__ __forceinline__ float2 unpack2(unsigned long long v) {
    unsigned lo, hi;
    asm("mov.b64 {%0, %1}, %2;" : "=r"(lo), "=r"(hi) : "l"(v));
    return make_float2(__uint_as_float(lo), __uint_as_float(hi));
}

// ===========================================================================
// TF32x3 tensor-core GEMM: C = op(A[M,K] @ B[K,N] + bias), row-major fp32.
// CTA 128x128, 256 threads (8 warps, 4m x 2n), warp tile 32x64.
// BK=16, cp.async double buffer. Fragment LDS conflict-free by stride choice:
//   A smem [row][k], ldk=20  (banks 20g+tig all-distinct per instr)
//   B smem [k][n],  ldn=136  (banks 8*tig+g all-distinct per instr)
// Precision: x = hi + lo (tf32 split); D = Ah*Bh + Al*Bh + Ah*Bl  (err~2^-22)
// gridDim=(N/128, M/128, Z); z splits K (Kper each), writes C + z*zCoff.
// Concat: column tile bn >= ncat reads B2 at (bn - ncat); bias indexed by
// output column.
// ===========================================================================
#define TM 128
#define TN 128
#define TBK 16
#define ALD 20                     // A smem words per row
#define BLD 136                    // B smem words per k-row
#define ASTG (TM*ALD)              // 2560 floats
#define BSTG (TBK*BLD)             // 2176 floats

template<bool RELU, bool HASBIAS>
__global__ __launch_bounds__(256) void gemm_mma(
    const float* __restrict__ A, int lda,
    const float* __restrict__ B, const float* __restrict__ B2,
    int ncat, int ldb,
    const float* __restrict__ bias,
    float* __restrict__ C, int ldc,
    int Kper, size_t zCoff)
{
    __shared__ float smA[2][ASTG];
    __shared__ float smB[2][BSTG];

    const int tid = threadIdx.x;
    const int wid = tid >> 5, lane = tid & 31;
    const int g = lane >> 2, tig = lane & 3;
    const int wm = (wid & 3) * 32;         // warp row offset in tile
    const int wn = (wid >> 2) * 64;        // warp col offset in tile

    const int bm = blockIdx.y * TM;
    int bn = blockIdx.x * TN;
    const int colg0 = bn;                  // output column base
    const int z = blockIdx.z;

    const float* Bsel = B;
    if (bn >= ncat) { Bsel = B2; bn -= ncat; }

    const float* Ab = A + (size_t)z * Kper + (size_t)bm * lda;
    const float* Bb = Bsel + (size_t)z * Kper * ldb + bn;
    float* Cb = C + (size_t)z * zCoff;

    float4 acc[2][8];                      // [m16-tile][n8-tile]
#pragma unroll
    for (int mt = 0; mt < 2; mt++)
#pragma unroll
        for (int n8 = 0; n8 < 8; n8++) acc[mt][n8] = make_float4(0.f, 0.f, 0.f, 0.f);

    const int CH = Kper / TBK;

    // stage fill: A 512 float4 (2/thread), B 512 float4 (2/thread)
#define CPA(k0, st) do { \
    uint32_t sa = smem_u32(&smA[st][0]); \
    uint32_t sb = smem_u32(&smB[st][0]); \
    _Pragma("unroll") \
    for (int q = 0; q < 2; q++) { \
        int idx = q * 256 + tid; \
        int m = idx >> 2, kq = (idx & 3) << 2; \
        cp_async16(sa + (uint32_t)(m * ALD + kq) * 4u, \
                   Ab + (size_t)m * lda + (k0) + kq); \
    } \
    _Pragma("unroll") \
    for (int q = 0; q < 2; q++) { \
        int idx = q * 256 + tid; \
        int k = idx >> 5, n4 = (idx & 31) << 2; \
        cp_async16(sb + (uint32_t)(k * BLD + n4) * 4u, \
                   Bb + (size_t)((k0) + k) * ldb + n4); \
    } \
    CP_COMMIT(); \
} while (0)

    CPA(0, 0);

    for (int c = 0; c < CH; c++) {
        const int st = c & 1;
        if (c + 1 < CH) {
            CPA((c + 1) * TBK, st ^ 1);
            CP_WAIT(1);
        } else {
            CP_WAIT(0);
        }
        __syncthreads();

        const float* As = smA[st];
        const float* Bs = smB[st];
#pragma unroll
        for (int ks = 0; ks < 2; ks++) {
            const int k0 = ks * 8;
            // ---- A fragments (hi/lo split) ----
            uint32_t ahi[2][4], alo[2][4];
#pragma unroll
            for (int mt = 0; mt < 2; mt++) {
                const float* ab = As + (wm + mt * 16 + g) * ALD + k0 + tig;
                float x0 = ab[0];
                float x1 = ab[8 * ALD];
                float x2 = ab[4];
                float x3 = ab[8 * ALD + 4];
                ahi[mt][0] = tf32u(x0); alo[mt][0] = tf32u(x0 - __uint_as_float(ahi[mt][0]));
                ahi[mt][1] = tf32u(x1); alo[mt][1] = tf32u(x1 - __uint_as_float(ahi[mt][1]));
                ahi[mt][2] = tf32u(x2); alo[mt][2] = tf32u(x2 - __uint_as_float(ahi[mt][2]));
                ahi[mt][3] = tf32u(x3); alo[mt][3] = tf32u(x3 - __uint_as_float(ahi[mt][3]));
            }
            // ---- B fragments per n8 tile, 3-term MMA ----
#pragma unroll
            for (int n8 = 0; n8 < 8; n8++) {
                const float* bb = Bs + (k0 + tig) * BLD + wn + n8 * 8 + g;
                float y0 = bb[0];
                float y1 = bb[4 * BLD];
                uint32_t bh0 = tf32u(y0), bh1 = tf32u(y1);
                uint32_t bl0 = tf32u(y0 - __uint_as_float(bh0));
                uint32_t bl1 = tf32u(y1 - __uint_as_float(bh1));
#pragma unroll
                for (int mt = 0; mt < 2; mt++) {
                    mma_tf32(acc[mt][n8], ahi[mt], bh0, bh1);
                    mma_tf32(acc[mt][n8], alo[mt], bh0, bh1);
                    mma_tf32(acc[mt][n8], ahi[mt], bl0, bl1);
                }
            }
        }
        __syncthreads();   // all warps done with stage st before overwrite
    }

    // ---- epilogue: regs -> global (float2 per c-pair) ----
#pragma unroll
    for (int n8 = 0; n8 < 8; n8++) {
        const int col = colg0 + wn + n8 * 8 + 2 * tig;
        float2 bv = make_float2(0.f, 0.f);
        if (HASBIAS) bv = *(const float2*)(bias + col);
#pragma unroll
        for (int mt = 0; mt < 2; mt++) {
            const int row = bm + wm + mt * 16 + g;
            float4 d = acc[mt][n8];
            float2 lo = make_float2(d.x + bv.x, d.y + bv.y);
            float2 hi = make_float2(d.z + bv.x, d.w + bv.y);
            if (RELU) {
                lo.x = fmaxf(lo.x, 0.f); lo.y = fmaxf(lo.y, 0.f);
                hi.x = fmaxf(hi.x, 0.f); hi.y = fmaxf(hi.y, 0.f);
            }
            *(float2*)(Cb + (size_t)row * ldc + col) = lo;
            *(float2*)(Cb + (size_t)(row + 8) * ldc + col) = hi;
        }
    }
#undef CPA
}

// ===========================================================================
// Prep: pair index table
// ===========================================================================
__global__ void prep_pairs_kernel()
{
    int p = blockIdx.x * blockDim.x + threadIdx.x;
    if (p >= NPAIR) return;
    int rem = p, i = 0;
    while (rem >= (Nent - 1) - i) { rem -= (Nent - 1) - i; i++; }
    g_pairs[p * 2]     = i;
    g_pairs[p * 2 + 1] = i + 1 + rem;
}

// ===========================================================================
// Combine split-K + bias + transpose:
//  in:  pK[0]+pK[1] at [e=(b,n)][k'] (k'<768 -> pA + b1r, else pB)
//  out: pAT[b][k][n], pBT[b][k][n]
// ===========================================================================
__global__ __launch_bounds__(256) void combine_transpose_kernel(
    const float* __restrict__ b1r)
{
    __shared__ float t[32][33];
    const int kb = blockIdx.x * 32;        // k' base 0..1535
    const int eb = blockIdx.y * 32;        // entity-row base 0..1023
    const int tx = threadIdx.x & 31;
    const int ty = threadIdx.x >> 5;       // 0..7

#pragma unroll
    for (int s = 0; s < 4; s++) {
        int e = eb + ty + s * 8;
        size_t off = (size_t)e * PAIRN + kb + tx;
        t[ty + s * 8][tx] = g_pK[0][off] + g_pK[1][off];
    }
    __syncthreads();

    const int b = eb >> 6;
    const int n0 = eb & 63;
#pragma unroll
    for (int s = 0; s < 4; s++) {
        int kk = kb + ty + s * 8;
        float v = t[tx][ty + s * 8];
        if (kk < Hdim) {
            v += b1r[kk];
            g_pAT[((size_t)b * Hdim + kk) * Nent + n0 + tx] = v;
        } else {
            g_pBT[((size_t)b * Hdim + (kk - Hdim)) * Nent + n0 + tx] = v;
        }
    }
}

// ===========================================================================
// entity_logits = hidden[8192,384] @ W2e[384,9] + b2e. Warp per row.
// ===========================================================================
__global__ __launch_bounds__(256) void entity_logits_kernel(
    const float* __restrict__ hidden, const float* __restrict__ W2e,
    const float* __restrict__ b2e, float* __restrict__ out)
{
    __shared__ float W2s[HH * ET];
    const int tid = threadIdx.x;
    for (int i = tid; i < HH * ET; i += 256) W2s[i] = W2e[i];
    __syncthreads();

    const int warp = tid >> 5, lane = tid & 31;
    const int row = blockIdx.x * 8 + warp;
    const float* hrow = hidden + (size_t)row * HH;

    float acc[ET];
#pragma unroll
    for (int c = 0; c < ET; c++) acc[c] = 0.f;

#pragma unroll
    for (int kk = 0; kk < HH / 32; kk++) {
        int k = kk * 32 + lane;
        float h = hrow[k];
        const float* w = &W2s[k * ET];
#pragma unroll
        for (int c = 0; c < ET; c++) acc[c] += h * w[c];
    }
#pragma unroll
    for (int c = 0; c < ET; c++)
#pragma unroll
        for (int off = 16; off > 0; off >>= 1)
            acc[c] += __shfl_down_sync(0xffffffffu, acc[c], off);

    if (lane == 0) {
        float* o = out + (size_t)row * ET;
#pragma unroll
        for (int c = 0; c < ET; c++) o[c] = acc[c] + b2e[c];
    }
}

// ===========================================================================
// Span mean pooling, fixed 16-iteration predicated loop.
// ===========================================================================
__global__ __launch_bounds__(192) void span_pool_kernel(
    const float4* __restrict__ seq4, const int* __restrict__ spans,
    float4* __restrict__ er4)
{
    const int bn = blockIdx.x;
    const int b = bn >> 6;
    const int s0 = spans[bn * 2];
    const int s1 = spans[bn * 2 + 1];
    int cnt = s1 - s0; if (cnt < 1) cnt = 1;
    const float inv = 1.f / (float)cnt;
    const float4* base = seq4 + (size_t)b * Ssz * (Hdim / 4) + threadIdx.x;

    float4 acc = make_float4(0.f, 0.f, 0.f, 0.f);
#pragma unroll
    for (int q = 0; q < 16; q++) {
        int s = s0 + q;
        float4 v = base[(size_t)s * (Hdim / 4)];
        if (s < s1) { acc.x += v.x; acc.y += v.y; acc.z += v.z; acc.w += v.w; }
    }
    acc.x *= inv; acc.y *= inv; acc.z *= inv; acc.w *= inv;
    er4[(size_t)bn * (Hdim / 4) + threadIdx.x] = acc;
}

// ===========================================================================
// relation_logits: thread per pair, W2 broadcast from smem, FFMA2 accs.
// h(k) = relu(pAT[b][k][i] + pBT[b][k][j]);  logits = h @ W2r + b2r
// ===========================================================================
__global__ __launch_bounds__(256) void relation_kernel(
    const float* __restrict__ W2r, const float* __restrict__ b2r,
    float* __restrict__ out)
{
    __shared__ __align__(16) float Wp[Hdim * 12];      // [k][12] padded
    const int tid = threadIdx.x;
    for (int idx = tid; idx < Hdim * 12; idx += 256) {
        int k = idx / 12, c = idx % 12;
        Wp[idx] = (c < RT) ? W2r[k * RT + c] : 0.f;
    }
    __syncthreads();

    const int b = blockIdx.y;
    const int p = blockIdx.x * 256 + tid;
    const bool act = (p < NPAIR);
    int i = 0, j = 0;
    if (act) { i = g_pairs[p * 2]; j = g_pairs[p * 2 + 1]; }

    const float* At = g_pAT + (size_t)b * Hdim * Nent;
    const float* Bt = g_pBT + (size_t)b * Hdim * Nent;

    unsigned long long acc[6];
#pragma unroll
    for (int c = 0; c < 6; c++) acc[c] = 0ull;

#pragma unroll 4
    for (int k = 0; k < Hdim; k++) {
        float h = fmaxf(At[(size_t)k * Nent + i] + Bt[(size_t)k * Nent + j], 0.f);
        unsigned long long hd = dup2(h);
        const ulonglong2* w = (const ulonglong2*)&Wp[k * 12];
        ulonglong2 w0 = w[0], w1 = w[1], w2 = w[2];
        ffma2(acc[0], hd, w0.x); ffma2(acc[1], hd, w0.y);
        ffma2(acc[2], hd, w1.x); ffma2(acc[3], hd, w1.y);
        ffma2(acc[4], hd, w2.x); ffma2(acc[5], hd, w2.y);
    }

    if (act) {
        float o[12];
#pragma unroll
        for (int c = 0; c < 6; c++) {
            float2 v = unpack2(acc[c]);
            o[c * 2] = v.x; o[c * 2 + 1] = v.y;
        }
        float* dst = out + (size_t)(b * NPAIR + p) * RT;
#pragma unroll
        for (int c = 0; c < RT; c++) dst[c] = o[c] + b2r[c];
    }
}

// ===========================================================================
extern "C" void kernel_launch(void* const* d_in, const int* in_sizes, int n_in,
                              void* d_out, int out_size)
{
    const float* seq   = (const float*)d_in[0];
    const int*   spans = (const int*)d_in[2];
    const float* W1e   = (const float*)d_in[3];
    const float* b1e   = (const float*)d_in[4];
    const float* W2e   = (const float*)d_in[5];
    const float* b2e   = (const float*)d_in[6];
    const float* W1r   = (const float*)d_in[7];
    const float* b1r   = (const float*)d_in[8];
    const float* W2r   = (const float*)d_in[9];
    const float* b2r   = (const float*)d_in[10];

    float* out = (float*)d_out;
    float* EL = out;                                   // [16,512,9]
    float* ER = out + (size_t)MS * ET;                 // [16,64,768]
    float* RL = ER + (size_t)ME * Hdim;                // [16,2016,10]

    void *p_hidden, *p_pK;
    cudaGetSymbolAddress(&p_hidden, g_hidden);
    cudaGetSymbolAddress(&p_pK, g_pK);
    float* hidden = (float*)p_hidden;

    // Prep
    prep_pairs_kernel<<<(NPAIR + 255) / 256, 256>>>();

    // entity_repr (output + input of pair GEMM)
    span_pool_kernel<<<Bsz * Nent, 192>>>((const float4*)seq, spans, (float4*)ER);

    // hidden = relu(seq @ W1e + b1e)   [8192,384]  tensor-core TF32x3
    gemm_mma<true, true><<<dim3(HH / TN, MS / TM, 1), 256>>>(
        seq, Hdim, W1e, nullptr, 1 << 30, HH, b1e, hidden, HH, Hdim, 0);

    // entity_logits = hidden @ W2e + b2e
    entity_logits_kernel<<<MS / 8, 256>>>(hidden, W2e, b2e, EL);

    // pK[z] = ER @ [W1r_top | W1r_bot](z-slice)   split-K=2
    gemm_mma<false, false><<<dim3(PAIRN / TN, ME / TM, 2), 256>>>(
        ER, Hdim, W1r, W1r + (size_t)Hdim * Hdim, Hdim, Hdim, nullptr,
        (float*)p_pK, PAIRN, Hdim / 2, (size_t)ME * PAIRN);

    // pAT/pBT = transpose(pK[0] + pK[1] + [b1r | 0])
    combine_transpose_kernel<<<dim3(PAIRN / 32, ME / 32), 256>>>(b1r);

    // relation_logits
    relation_kernel<<<dim3((NPAIR + 255) / 256, Bsz), 256>>>(W2r, b2r, RL);
}

// round 7
// speedup vs baseline: 1.4543x; 1.1299x over previous
#include <cuda_runtime.h>
#include <cstdint>
#include <cstddef>

// Problem constants
#define Bsz 16
#define Ssz 512
#define Nent 64
#define Hdim 768
#define HH 384          // H/2
#define ET 9
#define RT 10
#define NPAIR 2016      // 64*63/2
#define MS (Bsz*Ssz)    // 8192
#define ME (Bsz*Nent)   // 1024
#define PAIRN (2*Hdim)  // 1536
#define ZPAIR 4         // split-K factor, pair GEMM
#define ZE 2            // split-K factor, entity GEMM

// Scratch (static device arrays — allocation-free rule)
__device__ float g_eK[ZE][(size_t)MS * HH];            // entity GEMM split-K partials
__device__ float g_pK[ZPAIR][(size_t)ME * PAIRN];      // pair GEMM split-K partials
__device__ float g_pAT[(size_t)Bsz * Hdim * Nent];     // pA transposed [b][k][n]
__device__ float g_pBT[(size_t)Bsz * Hdim * Nent];     // pB transposed [b][k][n]
__device__ int   g_pairs[NPAIR * 2];

// ===========================================================================
// Packed fp32x2 + cp.async helpers (base-ISA PTX)
// ===========================================================================
__device__ __forceinline__ void ffma2(unsigned long long& d,
                                      unsigned long long a,
                                      unsigned long long b) {
    asm("fma.rn.f32x2 %0, %1, %2, %0;" : "+l"(d) : "l"(a), "l"(b));
}
__device__ __forceinline__ unsigned long long dup2(float x) {
    unsigned long long r; unsigned u = __float_as_uint(x);
    asm("mov.b64 %0, {%1, %1};" : "=l"(r) : "r"(u));
    return r;
}
__device__ __forceinline__ float2 unpack2(unsigned long long v) {
    unsigned lo, hi;
    asm("mov.b64 {%0, %1}, %2;" : "=r"(lo), "=r"(hi) : "l"(v));
    return make_float2(__uint_as_float(lo), __uint_as_float(hi));
}
__device__ __forceinline__ uint32_t smem_u32(const void* p) {
    uint32_t a;
    asm("{ .reg .u64 t; cvta.to.shared.u64 t, %1; cvt.u32.u64 %0, t; }"
        : "=r"(a) : "l"(p));
    return a;
}
__device__ __forceinline__ void cp_async16(uint32_t saddr, const void* gaddr) {
    asm volatile("cp.async.cg.shared.global [%0], [%1], 16;"
                 :: "r"(saddr), "l"(gaddr) : "memory");
}
#define CP_COMMIT() asm volatile("cp.async.commit_group;" ::: "memory")
#define CP_WAIT0()  asm volatile("cp.async.wait_group 0;" ::: "memory")

// ===========================================================================
// FFMA2 SGEMM (R4 engine, verified 103us config): C = A[M,K] @ B[K,N].
// CTA tile 64x128, BK=32, 128 threads, microtile rows {4lm+j}∪{32+4lm+j} x 8.
// A LDG->STS transposed+swizzled; B streams via cp.async.
// gridDim=(N/128, M/64, Z); z splits K (Kper each), writes C + z*zCoff.
// Concat: column tile bn >= ncat reads B2 at (bn - ncat).
// ===========================================================================
#define GTM 64
#define GTN 128
#define GTK 32
#define ASTRIDE 68                     // words per k-row of A smem
#define ASTAGE (GTK*ASTRIDE)           // 2176 floats
#define BSTAGE (GTK*GTN)               // 4096 floats
#define GEMM_SMEM ((2*ASTAGE + 2*BSTAGE) * 4)   // 50176 bytes

__global__ __launch_bounds__(128) void gemm_f2(
    const float* __restrict__ A, int lda,
    const float* __restrict__ B, const float* __restrict__ B2,
    int ncat, int ldb,
    float* __restrict__ C, int ldc,
    int Kper, size_t zCoff)
{
    extern __shared__ float sm[];
    float* smA = sm;                   // 2 stages x ASTAGE
    float* smB = sm + 2 * ASTAGE;      // 2 stages x BSTAGE

    const int tid = threadIdx.x;
    const int wid = tid >> 5, lane = tid & 31;
    const int lm = lane >> 2;          // 0..7
    const int ln = lane & 3;           // 0..3
    const int col0 = wid * 32 + ln * 8;

    const int bm = blockIdx.y * GTM;
    int bn = blockIdx.x * GTN;
    const int colg0 = bn;              // output column base
    const int z = blockIdx.z;

    const float* Bsel = B;
    if (bn >= ncat) { Bsel = B2; bn -= ncat; }

    const float* Ab = A + (size_t)z * Kper + (size_t)bm * lda;
    const float* Bb = Bsel + (size_t)z * Kper * ldb + bn;
    float* Cb = C + (size_t)z * zCoff;

    unsigned long long acc[4][8];      // [row-pair][col]
#pragma unroll
    for (int r = 0; r < 4; r++)
#pragma unroll
        for (int c = 0; c < 8; c++) acc[r][c] = 0ull;

    const int CH = Kper / GTK;
    float4 ra[4];

    // A: 64x32 tile = 512 float4; idx=q*128+tid -> m=idx>>3, kq=(idx&7)*4
#define LDG_A(k0) do { \
    _Pragma("unroll") \
    for (int q = 0; q < 4; q++) { \
        int idx = q * 128 + tid; \
        int m = idx >> 3, kq = (idx & 7) << 2; \
        ra[q] = *(const float4*)(Ab + (size_t)m * lda + (k0) + kq); \
    } \
} while (0)
    // STS transposed + swizzle: addr(k,m) = k*68 + (m ^ (k & 28))
#define STS_A(dst) do { \
    _Pragma("unroll") \
    for (int q = 0; q < 4; q++) { \
        int idx = q * 128 + tid; \
        int m = idx >> 3, kq = (idx & 7) << 2; \
        int ms = m ^ kq; \
        (dst)[(kq + 0) * ASTRIDE + ms] = ra[q].x; \
        (dst)[(kq + 1) * ASTRIDE + ms] = ra[q].y; \
        (dst)[(kq + 2) * ASTRIDE + ms] = ra[q].z; \
        (dst)[(kq + 3) * ASTRIDE + ms] = ra[q].w; \
    } \
} while (0)
    // B: 32x128 tile = 1024 float4; idx=q*128+tid -> k=idx>>5, c4=(idx&31)*4
#define CPA_B(k0, stB) do { \
    uint32_t sb = smem_u32(smB + (stB) * BSTAGE) + (uint32_t)tid * 16u; \
    _Pragma("unroll") \
    for (int q = 0; q < 8; q++) { \
        int idx = q * 128 + tid; \
        int k = idx >> 5, c4 = (idx & 31) << 2; \
        cp_async16(sb + q * 2048u, Bb + (size_t)((k0) + k) * ldb + c4); \
    } \
    CP_COMMIT(); \
} while (0)

    // ---- prologue ----
    CPA_B(0, 0);
    LDG_A(0);
    STS_A(smA);
    CP_WAIT0();
    __syncthreads();

    for (int c = 0; c < CH; c++) {
        const int st = c & 1;
        const int nx = st ^ 1;
        if (c + 1 < CH) {
            CPA_B((c + 1) * GTK, nx);
            LDG_A((c + 1) * GTK);
        }

        const float* Asm = smA + st * ASTAGE;
        const float* Bsm = smB + st * BSTAGE;
#pragma unroll
        for (int k = 0; k < GTK; k++) {
            const int sw = k & 28;
            ulonglong2 ap0 = *(const ulonglong2*)&Asm[k * ASTRIDE + ((4 * lm) ^ sw)];
            ulonglong2 ap1 = *(const ulonglong2*)&Asm[k * ASTRIDE + (32 + ((4 * lm) ^ sw))];
            float4 b0 = *(const float4*)&Bsm[k * GTN + col0];
            float4 b1 = *(const float4*)&Bsm[k * GTN + col0 + 4];
            unsigned long long bd[8];
            bd[0] = dup2(b0.x); bd[1] = dup2(b0.y); bd[2] = dup2(b0.z); bd[3] = dup2(b0.w);
            bd[4] = dup2(b1.x); bd[5] = dup2(b1.y); bd[6] = dup2(b1.z); bd[7] = dup2(b1.w);
            unsigned long long ap[4] = {ap0.x, ap0.y, ap1.x, ap1.y};
#pragma unroll
            for (int r = 0; r < 4; r++)
#pragma unroll
                for (int cc = 0; cc < 8; cc++)
                    ffma2(acc[r][cc], ap[r], bd[cc]);
        }

        if (c + 1 < CH) STS_A(smA + nx * ASTAGE);
        CP_WAIT0();
        __syncthreads();
    }

    // ---- epilogue (raw partials, no bias/relu — handled downstream) ----
    const int colg = colg0 + col0;
#pragma unroll
    for (int rp = 0; rp < 4; rp++) {
        int r0 = (rp < 2) ? (4 * lm + 2 * rp) : (32 + 4 * lm + 2 * (rp - 2));
        float lo[8], hi[8];
#pragma unroll
        for (int cc = 0; cc < 8; cc++) {
            float2 v = unpack2(acc[rp][cc]);
            lo[cc] = v.x;
            hi[cc] = v.y;
        }
        float* C0 = Cb + (size_t)(bm + r0) * ldc + colg;
        float* C1 = Cb + (size_t)(bm + r0 + 1) * ldc + colg;
        *(float4*)C0 = make_float4(lo[0], lo[1], lo[2], lo[3]);
        *(float4*)(C0 + 4) = make_float4(lo[4], lo[5], lo[6], lo[7]);
        *(float4*)C1 = make_float4(hi[0], hi[1], hi[2], hi[3]);
        *(float4*)(C1 + 4) = make_float4(hi[4], hi[5], hi[6], hi[7]);
    }
#undef LDG_A
#undef STS_A
#undef CPA_B
}

// ===========================================================================
// Prep: pair index table
// ===========================================================================
__global__ void prep_pairs_kernel()
{
    int p = blockIdx.x * blockDim.x + threadIdx.x;
    if (p >= NPAIR) return;
    int rem = p, i = 0;
    while (rem >= (Nent - 1) - i) { rem -= (Nent - 1) - i; i++; }
    g_pairs[p * 2]     = i;
    g_pairs[p * 2 + 1] = i + 1 + rem;
}

// ===========================================================================
// Combine pair split-K partials + bias + transpose:
//  in:  sum_z pK[z] at [e=(b,n)][k'] (k'<768 -> pA + b1r, else pB)
//  out: pAT[b][k][n], pBT[b][k][n]
// ===========================================================================
__global__ __launch_bounds__(256) void combine_transpose_kernel(
    const float* __restrict__ b1r)
{
    __shared__ float t[32][33];
    const int kb = blockIdx.x * 32;        // k' base 0..1535
    const int eb = blockIdx.y * 32;        // entity-row base 0..1023
    const int tx = threadIdx.x & 31;
    const int ty = threadIdx.x >> 5;       // 0..7

#pragma unroll
    for (int s = 0; s < 4; s++) {
        int e = eb + ty + s * 8;
        size_t off = (size_t)e * PAIRN + kb + tx;
        float v = g_pK[0][off];
#pragma unroll
        for (int zz = 1; zz < ZPAIR; zz++) v += g_pK[zz][off];
        t[ty + s * 8][tx] = v;
    }
    __syncthreads();

    const int b = eb >> 6;
    const int n0 = eb & 63;
#pragma unroll
    for (int s = 0; s < 4; s++) {
        int kk = kb + ty + s * 8;
        float v = t[tx][ty + s * 8];
        if (kk < Hdim) {
            v += b1r[kk];
            g_pAT[((size_t)b * Hdim + kk) * Nent + n0 + tx] = v;
        } else {
            g_pBT[((size_t)b * Hdim + (kk - Hdim)) * Nent + n0 + tx] = v;
        }
    }
}

// ===========================================================================
// Fused: h = relu(eK0 + eK1 + b1e); entity_logits = h @ W2e + b2e.
// Warp per row; `hidden` never materialized.
// ===========================================================================
__global__ __launch_bounds__(256) void entity_logits_fused_kernel(
    const float* __restrict__ b1e, const float* __restrict__ W2e,
    const float* __restrict__ b2e, float* __restrict__ out)
{
    __shared__ float W2s[HH * ET];       // 13.8 KB
    __shared__ float b1s[HH];
    const int tid = threadIdx.x;
    for (int i = tid; i < HH * ET; i += 256) W2s[i] = W2e[i];
    for (int i = tid; i < HH; i += 256) b1s[i] = b1e[i];
    __syncthreads();

    const int warp = tid >> 5, lane = tid & 31;
    const int row = blockIdx.x * 8 + warp;
    const float* e0 = g_eK[0] + (size_t)row * HH;
    const float* e1 = g_eK[1] + (size_t)row * HH;

    float acc[ET];
#pragma unroll
    for (int c = 0; c < ET; c++) acc[c] = 0.f;

#pragma unroll
    for (int kk = 0; kk < HH / 32; kk++) {
        int k = kk * 32 + lane;
        float h = fmaxf(e0[k] + e1[k] + b1s[k], 0.f);
        const float* w = &W2s[k * ET];
#pragma unroll
        for (int c = 0; c < ET; c++) acc[c] += h * w[c];
    }
#pragma unroll
    for (int c = 0; c < ET; c++)
#pragma unroll
        for (int off = 16; off > 0; off >>= 1)
            acc[c] += __shfl_down_sync(0xffffffffu, acc[c], off);

    if (lane == 0) {
        float* o = out + (size_t)row * ET;
#pragma unroll
        for (int c = 0; c < ET; c++) o[c] = acc[c] + b2e[c];
    }
}

// ===========================================================================
// Span mean pooling, fixed 16-iteration predicated loop.
// ===========================================================================
__global__ __launch_bounds__(192) void span_pool_kernel(
    const float4* __restrict__ seq4, const int* __restrict__ spans,
    float4* __restrict__ er4)
{
    const int bn = blockIdx.x;
    const int b = bn >> 6;
    const int s0 = spans[bn * 2];
    const int s1 = spans[bn * 2 + 1];
    int cnt = s1 - s0; if (cnt < 1) cnt = 1;
    const float inv = 1.f / (float)cnt;
    const float4* base = seq4 + (size_t)b * Ssz * (Hdim / 4) + threadIdx.x;

    float4 acc = make_float4(0.f, 0.f, 0.f, 0.f);
#pragma unroll
    for (int q = 0; q < 16; q++) {
        int s = s0 + q;
        float4 v = base[(size_t)s * (Hdim / 4)];
        if (s < s1) { acc.x += v.x; acc.y += v.y; acc.z += v.z; acc.w += v.w; }
    }
    acc.x *= inv; acc.y *= inv; acc.z *= inv; acc.w *= inv;
    er4[(size_t)bn * (Hdim / 4) + threadIdx.x] = acc;
}

// ===========================================================================
// relation_logits: thread per pair, W2 broadcast from smem, FFMA2 accs.
// h(k) = relu(pAT[b][k][i] + pBT[b][k][j]);  logits = h @ W2r + b2r
// ===========================================================================
__global__ __launch_bounds__(256) void relation_kernel(
    const float* __restrict__ W2r, const float* __restrict__ b2r,
    float* __restrict__ out)
{
    __shared__ __align__(16) float Wp[Hdim * 12];      // [k][12] padded
    const int tid = threadIdx.x;
    for (int idx = tid; idx < Hdim * 12; idx += 256) {
        int k = idx / 12, c = idx % 12;
        Wp[idx] = (c < RT) ? W2r[k * RT + c] : 0.f;
    }
    __syncthreads();

    const int b = blockIdx.y;
    const int p = blockIdx.x * 256 + tid;
    const bool act = (p < NPAIR);
    int i = 0, j = 0;
    if (act) { i = g_pairs[p * 2]; j = g_pairs[p * 2 + 1]; }

    const float* At = g_pAT + (size_t)b * Hdim * Nent;
    const float* Bt = g_pBT + (size_t)b * Hdim * Nent;

    unsigned long long acc[6];
#pragma unroll
    for (int c = 0; c < 6; c++) acc[c] = 0ull;

#pragma unroll 4
    for (int k = 0; k < Hdim; k++) {
        float h = fmaxf(At[(size_t)k * Nent + i] + Bt[(size_t)k * Nent + j], 0.f);
        unsigned long long hd = dup2(h);
        const ulonglong2* w = (const ulonglong2*)&Wp[k * 12];
        ulonglong2 w0 = w[0], w1 = w[1], w2 = w[2];
        ffma2(acc[0], hd, w0.x); ffma2(acc[1], hd, w0.y);
        ffma2(acc[2], hd, w1.x); ffma2(acc[3], hd, w1.y);
        ffma2(acc[4], hd, w2.x); ffma2(acc[5], hd, w2.y);
    }

    if (act) {
        float o[12];
#pragma unroll
        for (int c = 0; c < 6; c++) {
            float2 v = unpack2(acc[c]);
            o[c * 2] = v.x; o[c * 2 + 1] = v.y;
        }
        float* dst = out + (size_t)(b * NPAIR + p) * RT;
#pragma unroll
        for (int c = 0; c < RT; c++) dst[c] = o[c] + b2r[c];
    }
}

// ===========================================================================
extern "C" void kernel_launch(void* const* d_in, const int* in_sizes, int n_in,
                              void* d_out, int out_size)
{
    const float* seq   = (const float*)d_in[0];
    const int*   spans = (const int*)d_in[2];
    const float* W1e   = (const float*)d_in[3];
    const float* b1e   = (const float*)d_in[4];
    const float* W2e   = (const float*)d_in[5];
    const float* b2e   = (const float*)d_in[6];
    const float* W1r   = (const float*)d_in[7];
    const float* b1r   = (const float*)d_in[8];
    const float* W2r   = (const float*)d_in[9];
    const float* b2r   = (const float*)d_in[10];

    float* out = (float*)d_out;
    float* EL = out;                                   // [16,512,9]
    float* ER = out + (size_t)MS * ET;                 // [16,64,768]
    float* RL = ER + (size_t)ME * Hdim;                // [16,2016,10]

    void *p_eK, *p_pK;
    cudaGetSymbolAddress(&p_eK, g_eK);
    cudaGetSymbolAddress(&p_pK, g_pK);

    cudaFuncSetAttribute(gemm_f2,
                         cudaFuncAttributeMaxDynamicSharedMemorySize, GEMM_SMEM);

    // Prep
    prep_pairs_kernel<<<(NPAIR + 255) / 256, 256>>>();

    // entity_repr (output + input of pair GEMM)
    span_pool_kernel<<<Bsz * Nent, 192>>>((const float4*)seq, spans, (float4*)ER);

    // eK[z] = seq @ W1e (z-th K-slice)   split-K=2, 768 CTAs
    gemm_f2<<<dim3(HH / GTN, MS / GTM, ZE), 128, GEMM_SMEM>>>(
        seq, Hdim, W1e, nullptr, 1 << 30, HH,
        (float*)p_eK, HH, Hdim / ZE, (size_t)MS * HH);

    // entity_logits = relu(eK0 + eK1 + b1e) @ W2e + b2e   (hidden fused away)
    entity_logits_fused_kernel<<<MS / 8, 256>>>(b1e, W2e, b2e, EL);

    // pK[z] = ER @ [W1r_top | W1r_bot](z-slice)   split-K=4, 768 CTAs
    gemm_f2<<<dim3(PAIRN / GTN, ME / GTM, ZPAIR), 128, GEMM_SMEM>>>(
        ER, Hdim, W1r, W1r + (size_t)Hdim * Hdim, Hdim, Hdim,
        (float*)p_pK, PAIRN, Hdim / ZPAIR, (size_t)ME * PAIRN);

    // pAT/pBT = transpose(sum_z pK[z] + [b1r | 0])
    combine_transpose_kernel<<<dim3(PAIRN / 32, ME / 32), 256>>>(b1r);

    // relation_logits
    relation_kernel<<<dim3((NPAIR + 255) / 256, Bsz), 256>>>(W2r, b2r, RL);
}